// round 1
// baseline (speedup 1.0000x reference)
#include <cuda_runtime.h>

// ---------------------------------------------------------------------------
// Loss_54494545052046: masked L1(preds,targets) + 0.1 * MSE(bone directions)
//   preds, targets: (B, T, 150) fp32 ; out: scalar fp32
//   m  = (targets != 0)
//   pm = preds*m ; tm = targets*m (== targets)
//   per frame: 50 bones, diff = J[ba]-J[bb], dir = diff/(|diff|+tiny)
//   pd/td masked by m at flat index 3*bone+c
//   loss = mean|pm-tm| + 0.1*mean((pd*m - td*m)^2)
// HBM-bound: ~315 MB read -> floor ~40-52 us on GB300.
// ---------------------------------------------------------------------------

#define FRAMES   32          // frames per block tile
#define NT       256         // threads per block
#define ST       151         // shared row stride (odd: decorrelate banks)
#define MAXB     8192        // max partial slots

__constant__ int c_ba[50] = {
    0,1,2,3,1,5,6,
    7, 8,9,10,11, 8,13,14,15, 8,17,18,19, 8,21,22,23, 8,25,26,27,
    4, 29,30,31,32, 29,34,35,36, 29,38,39,40, 29,42,43,44, 29,46,47,48,
    0
};
__constant__ int c_bb[50] = {
    1,2,3,4,5,6,7,
    8, 9,10,11,12, 13,14,15,16, 17,18,19,20, 21,22,23,24, 25,26,27,28,
    29, 30,31,32,33, 34,35,36,37, 38,39,40,41, 42,43,44,45, 46,47,48,49,
    2
};

__device__ double g_partial[2 * MAXB];

__global__ __launch_bounds__(NT)
void loss_main(const float* __restrict__ preds,
               const float* __restrict__ targets,
               int n_frames, int n_tiles)
{
    __shared__ float s_pm[FRAMES * ST];
    __shared__ float s_tm[FRAMES * ST];
    __shared__ double s_ra[NT / 32];
    __shared__ double s_rb[NT / 32];

    const float tiny = 1.17549435e-38f;   // jnp.finfo(float32).tiny
    float l1 = 0.f;
    float mse = 0.f;

    const int tid = threadIdx.x;

    for (int tile = blockIdx.x; tile < n_tiles; tile += gridDim.x) {
        const long long base = (long long)tile * (FRAMES * 150);
        const int valid = min(FRAMES, n_frames - tile * FRAMES);

        if (valid == FRAMES) {
            // Fast path: tile is 4800 consecutive floats, 16B-aligned -> float4.
            const float4* gp = (const float4*)(preds + base);
            const float4* gt = (const float4*)(targets + base);
            #pragma unroll 1
            for (int i = tid; i < (FRAMES * 150) / 4; i += NT) {
                float4 p = gp[i];
                float4 t = gt[i];
                const int e = i * 4;
                float pv[4] = {p.x, p.y, p.z, p.w};
                float tv[4] = {t.x, t.y, t.z, t.w};
                #pragma unroll
                for (int j = 0; j < 4; j++) {
                    const int idx = e + j;
                    const int f = idx / 150;
                    const int k = idx - f * 150;
                    const float tval = tv[j];
                    const float pmv = (tval != 0.f) ? pv[j] : 0.f;
                    l1 += fabsf(pmv - tval);      // tval==0 -> |0-0| = 0
                    s_pm[f * ST + k] = pmv;
                    s_tm[f * ST + k] = tval;
                }
            }
        } else {
            // Tail path (unused for 262144 frames, kept for generality).
            const int nfl = valid * 150;
            for (int i = tid; i < nfl; i += NT) {
                const float tval = targets[base + i];
                const float pval = preds[base + i];
                const float pmv = (tval != 0.f) ? pval : 0.f;
                l1 += fabsf(pmv - tval);
                const int f = i / 150;
                const int k = i - f * 150;
                s_pm[f * ST + k] = pmv;
                s_tm[f * ST + k] = tval;
            }
        }
        __syncthreads();

        // Bone phase: valid*50 tasks.
        const int ntask = valid * 50;
        #pragma unroll 1
        for (int task = tid; task < ntask; task += NT) {
            const int f = task / 50;
            const int bone = task - f * 50;
            const int ja = c_ba[bone] * 3;
            const int jb = c_bb[bone] * 3;
            const float* pr = s_pm + f * ST;
            const float* tr = s_tm + f * ST;

            const float dp0 = pr[ja + 0] - pr[jb + 0];
            const float dp1 = pr[ja + 1] - pr[jb + 1];
            const float dp2 = pr[ja + 2] - pr[jb + 2];
            const float dt0 = tr[ja + 0] - tr[jb + 0];
            const float dt1 = tr[ja + 1] - tr[jb + 1];
            const float dt2 = tr[ja + 2] - tr[jb + 2];

            const float invp = 1.f / (sqrtf(dp0*dp0 + dp1*dp1 + dp2*dp2) + tiny);
            const float invt = 1.f / (sqrtf(dt0*dt0 + dt1*dt1 + dt2*dt2) + tiny);

            // Direction mask uses targets at flat index 3*bone + c.
            const int mb = bone * 3;
            if (tr[mb + 0] != 0.f) { float d = dp0*invp - dt0*invt; mse += d*d; }
            if (tr[mb + 1] != 0.f) { float d = dp1*invp - dt1*invt; mse += d*d; }
            if (tr[mb + 2] != 0.f) { float d = dp2*invp - dt2*invt; mse += d*d; }
        }
        __syncthreads();
    }

    // Deterministic block reduction to doubles.
    double a = (double)l1;
    double b = (double)mse;
    #pragma unroll
    for (int off = 16; off > 0; off >>= 1) {
        a += __shfl_down_sync(0xffffffffu, a, off);
        b += __shfl_down_sync(0xffffffffu, b, off);
    }
    const int lane = tid & 31;
    const int wid  = tid >> 5;
    if (lane == 0) { s_ra[wid] = a; s_rb[wid] = b; }
    __syncthreads();
    if (wid == 0) {
        a = (lane < NT / 32) ? s_ra[lane] : 0.0;
        b = (lane < NT / 32) ? s_rb[lane] : 0.0;
        #pragma unroll
        for (int off = 4; off > 0; off >>= 1) {
            a += __shfl_down_sync(0xffffffffu, a, off);
            b += __shfl_down_sync(0xffffffffu, b, off);
        }
        if (lane == 0) {
            g_partial[blockIdx.x] = a;
            g_partial[MAXB + blockIdx.x] = b;
        }
    }
}

__global__ __launch_bounds__(256)
void loss_final(float* __restrict__ out, int nblocks, double invN)
{
    __shared__ double s_ra[8];
    __shared__ double s_rb[8];
    double a = 0.0, b = 0.0;
    for (int i = threadIdx.x; i < nblocks; i += 256) {
        a += g_partial[i];
        b += g_partial[MAXB + i];
    }
    #pragma unroll
    for (int off = 16; off > 0; off >>= 1) {
        a += __shfl_down_sync(0xffffffffu, a, off);
        b += __shfl_down_sync(0xffffffffu, b, off);
    }
    const int lane = threadIdx.x & 31;
    const int wid  = threadIdx.x >> 5;
    if (lane == 0) { s_ra[wid] = a; s_rb[wid] = b; }
    __syncthreads();
    if (wid == 0) {
        a = (lane < 8) ? s_ra[lane] : 0.0;
        b = (lane < 8) ? s_rb[lane] : 0.0;
        #pragma unroll
        for (int off = 4; off > 0; off >>= 1) {
            a += __shfl_down_sync(0xffffffffu, a, off);
            b += __shfl_down_sync(0xffffffffu, b, off);
        }
        if (lane == 0) {
            out[0] = (float)((a + 0.1 * b) * invN);
        }
    }
}

extern "C" void kernel_launch(void* const* d_in, const int* in_sizes, int n_in,
                              void* d_out, int out_size)
{
    const float* preds   = (const float*)d_in[0];
    const float* targets = (const float*)d_in[1];
    float* out = (float*)d_out;

    const int n = in_sizes[0];              // B*T*150
    const int n_frames = n / 150;           // 262144
    const int n_tiles  = (n_frames + FRAMES - 1) / FRAMES;  // 8192
    const int grid = (n_tiles < MAXB) ? n_tiles : MAXB;

    loss_main<<<grid, NT>>>(preds, targets, n_frames, n_tiles);
    loss_final<<<1, 256>>>(out, grid, 1.0 / (double)n);
}

// round 2
// speedup vs baseline: 2.7391x; 2.7391x over previous
#include <cuda_runtime.h>

// ---------------------------------------------------------------------------
// Loss_54494545052046 fused single-kernel:
//   loss = mean|pm - t| + 0.1 * mean((dir(pm) - dir(t))^2 per-bone)
// Design:
//   - tile = 32 frames (=warp lanes), 256 threads, persistent grid
//   - phase A: stream tile -> shared (flat, STS.128, conflict-free) + L1 term
//   - phase B: warp w = skeleton-chain role w, lane = frame; rsqrtf dirs
//   - +4 float pad for frames>=16 kills the 2-way (l, l+16) bank conflict
//   - last-block finalize (deterministic fixed-order sum), counter reset
// ---------------------------------------------------------------------------

#define FRAMES  32
#define NT      256
#define SROW    150
#define TILE_F4 1200          // 32*150/4
#define HALF_E  2400          // element index where pad kicks in (frame 16)
#define MAXB    1024

__device__ double       g_pa[MAXB];
__device__ double       g_pb[MAXB];
__device__ unsigned int g_count = 0;

// --- bone walk macros (registers: A = prev joint, B = new joint) -----------
#define LDA(j)  do { pax = pp[3*(j)];   pay = pp[3*(j)+1]; paz = pp[3*(j)+2]; \
                     tax = tp[3*(j)];   tay = tp[3*(j)+1]; taz = tp[3*(j)+2]; } while(0)
#define LDB(j)  do { pbx = pp[3*(j)];   pby = pp[3*(j)+1]; pbz = pp[3*(j)+2]; \
                     tbx = tp[3*(j)];   tby = tp[3*(j)+1]; tbz = tp[3*(j)+2]; } while(0)
#define SHIFT() do { pax = pbx; pay = pby; paz = pbz; \
                     tax = tbx; tay = tby; taz = tbz; } while(0)
#define EMIT()  do { \
    float dpx = pax - pbx, dpy = pay - pby, dpz = paz - pbz; \
    float dtx = tax - tbx, dty = tay - tby, dtz = taz - tbz; \
    float lp = dpx*dpx + dpy*dpy + dpz*dpz; \
    float lt = dtx*dtx + dty*dty + dtz*dtz; \
    float ip = (lp > 0.f) ? rsqrtf(lp) : 0.f; \
    float it = (lt > 0.f) ? rsqrtf(lt) : 0.f; \
    float dx = dpx*ip - dtx*it; \
    float dy = dpy*ip - dty*it; \
    float dz = dpz*ip - dtz*it; \
    mse += dx*dx + dy*dy + dz*dz; \
} while(0)
#define BF(a,b) do { LDA(a); LDB(b); EMIT(); } while(0)   // chain start
#define BN(b)   do { SHIFT(); LDB(b); EMIT(); } while(0)  // chain continue

__global__ __launch_bounds__(NT)
void loss_kernel(const float* __restrict__ preds,
                 const float* __restrict__ targets,
                 float* __restrict__ out,
                 int n_frames, int n_tiles, double invN)
{
    __shared__ float  s_pm[FRAMES * SROW + 4];
    __shared__ float  s_tm[FRAMES * SROW + 4];
    __shared__ double s_ra[NT / 32];
    __shared__ double s_rb[NT / 32];
    __shared__ int    s_last;

    const int tid  = threadIdx.x;
    const int lane = tid & 31;
    const int wid  = tid >> 5;

    float l1 = 0.f, mse = 0.f;

    for (int tile = blockIdx.x; tile < n_tiles; tile += gridDim.x) {
        const long long base  = (long long)tile * (FRAMES * SROW);
        const int       valid = min(FRAMES, n_frames - tile * FRAMES);

        // ---- phase A: global -> shared (masked), L1 accumulation ----
        if (valid == FRAMES) {
            const float4* gp = (const float4*)(preds + base);
            const float4* gt = (const float4*)(targets + base);
            #pragma unroll 1
            for (int i = tid; i < TILE_F4; i += NT) {
                float4 p = gp[i];
                float4 t = gt[i];
                float4 q;
                q.x = (t.x != 0.f) ? p.x : 0.f;
                q.y = (t.y != 0.f) ? p.y : 0.f;
                q.z = (t.z != 0.f) ? p.z : 0.f;
                q.w = (t.w != 0.f) ? p.w : 0.f;
                l1 += fabsf(q.x - t.x) + fabsf(q.y - t.y)
                    + fabsf(q.z - t.z) + fabsf(q.w - t.w);
                const int e    = i * 4;
                const int addr = e + ((e >= HALF_E) ? 4 : 0);
                *(float4*)(s_pm + addr) = q;
                *(float4*)(s_tm + addr) = t;
            }
        } else {
            const int nfl = valid * SROW;
            for (int i = tid; i < nfl; i += NT) {
                const float t = targets[base + i];
                const float p = preds[base + i];
                const float q = (t != 0.f) ? p : 0.f;
                l1 += fabsf(q - t);
                const int addr = i + ((i >= HALF_E) ? 4 : 0);
                s_pm[addr] = q;
                s_tm[addr] = t;
            }
        }
        __syncthreads();

        // ---- phase B: bone directions, warp = role, lane = frame ----
        if (lane < valid) {
            const float* pp = s_pm + lane * SROW + ((lane >= 16) ? 4 : 0);
            const float* tp = s_tm + lane * SROW + ((lane >= 16) ? 4 : 0);
            float pax, pay, paz, tax, tay, taz;
            float pbx, pby, pbz, tbx, tby, tbz;
            switch (wid) {
            case 0: // body chain 0-1-2-3-4  + pad bone (0,2)
                BF(0, 1); BN(2); BN(3); BN(4); BF(0, 2); break;
            case 1: // body chain 1-5-6-7 + (7,8) + (4,29)
                BF(1, 5); BN(6); BN(7); BN(8); BF(4, 29); break;
            case 2: // hand1 fingers 1,2
                BF(8, 9);  BN(10); BN(11); BN(12);
                BF(8, 13); BN(14); BN(15); BN(16); break;
            case 3: // hand1 fingers 3,4
                BF(8, 17); BN(18); BN(19); BN(20);
                BF(8, 21); BN(22); BN(23); BN(24); break;
            case 4: // hand1 finger 5, hand2 finger 1
                BF(8, 25);  BN(26); BN(27); BN(28);
                BF(29, 30); BN(31); BN(32); BN(33); break;
            case 5: // hand2 fingers 2,3
                BF(29, 34); BN(35); BN(36); BN(37);
                BF(29, 38); BN(39); BN(40); BN(41); break;
            case 6: // hand2 finger 4
                BF(29, 42); BN(43); BN(44); BN(45); break;
            default: // hand2 finger 5
                BF(29, 46); BN(47); BN(48); BN(49); break;
            }
        }
        __syncthreads();
    }

    // ---- block reduction (deterministic) ----
    double a = (double)l1;
    double b = (double)mse;
    #pragma unroll
    for (int off = 16; off > 0; off >>= 1) {
        a += __shfl_down_sync(0xffffffffu, a, off);
        b += __shfl_down_sync(0xffffffffu, b, off);
    }
    if (lane == 0) { s_ra[wid] = a; s_rb[wid] = b; }
    __syncthreads();
    if (wid == 0) {
        a = (lane < NT / 32) ? s_ra[lane] : 0.0;
        b = (lane < NT / 32) ? s_rb[lane] : 0.0;
        #pragma unroll
        for (int off = 4; off > 0; off >>= 1) {
            a += __shfl_down_sync(0xffffffffu, a, off);
            b += __shfl_down_sync(0xffffffffu, b, off);
        }
    }
    if (tid == 0) {
        g_pa[blockIdx.x] = a;
        g_pb[blockIdx.x] = b;
        __threadfence();
        const unsigned int old = atomicAdd(&g_count, 1u);
        s_last = (old == gridDim.x - 1) ? 1 : 0;
    }
    __syncthreads();

    // ---- last block finalizes (fixed-order sum -> deterministic) ----
    if (s_last) {
        double fa = 0.0, fb = 0.0;
        for (int i = tid; i < gridDim.x; i += NT) {
            fa += __ldcg(&g_pa[i]);
            fb += __ldcg(&g_pb[i]);
        }
        #pragma unroll
        for (int off = 16; off > 0; off >>= 1) {
            fa += __shfl_down_sync(0xffffffffu, fa, off);
            fb += __shfl_down_sync(0xffffffffu, fb, off);
        }
        if (lane == 0) { s_ra[wid] = fa; s_rb[wid] = fb; }
        __syncthreads();
        if (tid == 0) {
            fa = 0.0; fb = 0.0;
            #pragma unroll
            for (int w = 0; w < NT / 32; w++) { fa += s_ra[w]; fb += s_rb[w]; }
            out[0] = (float)((fa + 0.1 * fb) * invN);
            g_count = 0;   // reset for next graph replay
        }
    }
}

extern "C" void kernel_launch(void* const* d_in, const int* in_sizes, int n_in,
                              void* d_out, int out_size)
{
    const float* preds   = (const float*)d_in[0];
    const float* targets = (const float*)d_in[1];
    float* out = (float*)d_out;

    const int n        = in_sizes[0];                    // B*T*150
    const int n_frames = n / 150;                        // 262144
    const int n_tiles  = (n_frames + FRAMES - 1) / FRAMES;
    int grid = 148 * 5;                                  // 5 CTAs/SM (38.6KB smem)
    if (grid > n_tiles) grid = n_tiles;
    if (grid > MAXB)    grid = MAXB;

    loss_kernel<<<grid, NT>>>(preds, targets, out, n_frames, n_tiles,
                              1.0 / (double)n);
}